// round 1
// baseline (speedup 1.0000x reference)
#include <cuda_runtime.h>

// ---------------------------------------------------------------------------
// UMT5 encoder self-attention, fp32 baseline.
// Outputs: d_out[0 .. 4194304)              = attn_output [B,S,D]
//          d_out[4194304 .. 138412032)      = attn        [B,H,S,S]
// ---------------------------------------------------------------------------

#define kB  2
#define kS  2048
#define kD  1024
#define kH  16
#define kDK 64
#define kBH (kB * kH)
#define kNB (2 * kS - 1)          // 4095 relative-position deltas
#define kOUT0 ((long long)kB * kS * kD)   // 4194304

// Scratch (static device globals; no allocations anywhere)
__device__ float g_q[kBH * kS * kDK];
__device__ float g_k[kBH * kS * kDK];
__device__ float g_v[kBH * kS * kDK];
__device__ float g_ctx[kB * kS * kD];
__device__ float g_bias[kH * kNB];

// ---------------------------------------------------------------------------
// Bias table: g_bias[h][delta+2047] = rel_bias[bucket(delta)][h]
// Bucket boundaries done in integer arithmetic (matches correctly-rounded
// float32 reference exactly; boundaries at |d|=16,32,64 are exact in fp32).
// ---------------------------------------------------------------------------
__global__ void bias_kernel(const float* __restrict__ rel_bias) {
    int idx = blockIdx.x * blockDim.x + threadIdx.x;
    if (idx >= kH * kNB) return;
    int h = idx / kNB;
    int delta = idx % kNB - (kS - 1);
    int bucket = (delta > 0) ? 16 : 0;
    int a = delta < 0 ? -delta : delta;
    int add;
    if (a < 8)       add = a;
    else if (a < 12) add = 8;
    else if (a < 16) add = 9;
    else if (a < 23) add = 10;
    else if (a < 32) add = 11;
    else if (a < 46) add = 12;
    else if (a < 64) add = 13;
    else if (a < 91) add = 14;
    else             add = 15;
    bucket += add;
    g_bias[idx] = rel_bias[bucket * kH + h];
}

// ---------------------------------------------------------------------------
// SGEMM: C[4096x1024] = A[4096x1024] * W[1024x1024], fp32.
// BM=BN=64, BK=16, 256 threads, 4x4 micro-tile.
// scatter=1: write to [bh][s][dk] layout (QKV). scatter=0: row-major.
// ---------------------------------------------------------------------------
__global__ void __launch_bounds__(256) sgemm_kernel(
    const float* __restrict__ A, const float* __restrict__ W,
    float* __restrict__ C, int scatter)
{
    __shared__ float As[16][64];   // [k][m]
    __shared__ float Bs[16][64];   // [k][n]
    const int tid = threadIdx.x;
    const int tn = tid & 15, tm = tid >> 4;
    const int mBase = blockIdx.y * 64;
    const int nBase = blockIdx.x * 64;
    const int la_m = tid >> 2;
    const int la_k = (tid & 3) * 4;
    const int lb_k = tid >> 4;
    const int lb_n = (tid & 15) * 4;
    float acc[4][4] = {};

    for (int k0 = 0; k0 < kD; k0 += 16) {
        float4 av = *(const float4*)(A + (size_t)(mBase + la_m) * kD + k0 + la_k);
        float4 bv = *(const float4*)(W + (size_t)(k0 + lb_k) * kD + nBase + lb_n);
        As[la_k + 0][la_m] = av.x;
        As[la_k + 1][la_m] = av.y;
        As[la_k + 2][la_m] = av.z;
        As[la_k + 3][la_m] = av.w;
        *(float4*)&Bs[lb_k][lb_n] = bv;
        __syncthreads();
#pragma unroll
        for (int kk = 0; kk < 16; kk++) {
            float4 a = *(const float4*)&As[kk][tm * 4];
            float4 b = *(const float4*)&Bs[kk][tn * 4];
            float ar[4] = {a.x, a.y, a.z, a.w};
            float br[4] = {b.x, b.y, b.z, b.w};
#pragma unroll
            for (int i = 0; i < 4; i++)
#pragma unroll
                for (int j = 0; j < 4; j++)
                    acc[i][j] = fmaf(ar[i], br[j], acc[i][j]);
        }
        __syncthreads();
    }

    if (!scatter) {
#pragma unroll
        for (int i = 0; i < 4; i++) {
            int row = mBase + tm * 4 + i;
            *(float4*)(C + (size_t)row * kD + nBase + tn * 4) =
                make_float4(acc[i][0], acc[i][1], acc[i][2], acc[i][3]);
        }
    } else {
        int h = nBase >> 6;        // nBase is a multiple of 64
        int dk = tn * 4;
#pragma unroll
        for (int i = 0; i < 4; i++) {
            int row = mBase + tm * 4 + i;
            int b = row >> 11, s = row & (kS - 1);
            size_t dst = ((size_t)(b * kH + h) * kS + s) * kDK + dk;
            *(float4*)(C + dst) =
                make_float4(acc[i][0], acc[i][1], acc[i][2], acc[i][3]);
        }
    }
}

// ---------------------------------------------------------------------------
// Attention: per block = one (bh, 64-row q-tile).
// Phase 1: logits = QK^T + bias, online max/sum, raw logits -> attn buffer.
// Phase 2: normalize in place (final attn), accumulate ctx = P*V.
// All smem tiles natural layout, stride 68 (conflict-free / broadcast LDS).
// ---------------------------------------------------------------------------
__global__ void __launch_bounds__(256) attn_kernel(float* __restrict__ attn) {
    __shared__ float Pa[64][68];   // Q tile, then P tile  [m][d]/[m][k]
    __shared__ float Pb[64][68];   // K tile, then V tile  [n][d]/[k][d]
    __shared__ float Ms[64], Ls[64], Li[64];
    __shared__ float bias_s[128];

    const int bh = blockIdx.y;
    const int h = bh & (kH - 1);
    const int q0 = blockIdx.x * 64;
    const int tid = threadIdx.x;
    const int tn = tid & 15, tm = tid >> 4;

    const float* Qp = g_q + (size_t)bh * kS * kDK + (size_t)q0 * kDK;
    const float* Kp = g_k + (size_t)bh * kS * kDK;
    const float* Vp = g_v + (size_t)bh * kS * kDK;
    float* Ap = attn + (size_t)bh * kS * kS;

    // Load Q tile [64][64]
    {
        const float4* src = (const float4*)Qp;
#pragma unroll
        for (int r = 0; r < 4; r++) {
            int f4 = r * 256 + tid;
            int m = f4 >> 4;
            int d4 = (f4 & 15) << 2;
            *(float4*)&Pa[m][d4] = src[f4];
        }
    }
    if (tid < 64) { Ms[tid] = -3.0e38f; Ls[tid] = 0.0f; }
    __syncthreads();

    // ---------------- Phase 1 ----------------
    for (int kt = 0; kt < kS / 64; kt++) {
        {
            const float4* src = (const float4*)(Kp + (size_t)kt * 64 * kDK);
#pragma unroll
            for (int r = 0; r < 4; r++) {
                int f4 = r * 256 + tid;
                int m = f4 >> 4;
                int d4 = (f4 & 15) << 2;
                *(float4*)&Pb[m][d4] = src[f4];
            }
        }
        if (tid < 127)
            bias_s[tid] = g_bias[h * kNB + (kt * 64 - q0) + tid - 63 + (kS - 1)];
        __syncthreads();

        float sc[4][4] = {};
#pragma unroll
        for (int d4 = 0; d4 < 64; d4 += 4) {
            float4 qa[4], kb[4];
#pragma unroll
            for (int i = 0; i < 4; i++) qa[i] = *(const float4*)&Pa[tm * 4 + i][d4];
#pragma unroll
            for (int j = 0; j < 4; j++) kb[j] = *(const float4*)&Pb[tn * 4 + j][d4];
#pragma unroll
            for (int i = 0; i < 4; i++)
#pragma unroll
                for (int j = 0; j < 4; j++) {
                    sc[i][j] = fmaf(qa[i].x, kb[j].x, sc[i][j]);
                    sc[i][j] = fmaf(qa[i].y, kb[j].y, sc[i][j]);
                    sc[i][j] = fmaf(qa[i].z, kb[j].z, sc[i][j]);
                    sc[i][j] = fmaf(qa[i].w, kb[j].w, sc[i][j]);
                }
        }

#pragma unroll
        for (int i = 0; i < 4; i++) {
            int row = tm * 4 + i;
#pragma unroll
            for (int j = 0; j < 4; j++)
                sc[i][j] += bias_s[tn * 4 + j - row + 63];
            float mx = fmaxf(fmaxf(sc[i][0], sc[i][1]), fmaxf(sc[i][2], sc[i][3]));
#pragma unroll
            for (int off = 8; off; off >>= 1)
                mx = fmaxf(mx, __shfl_xor_sync(0xffffffffu, mx, off));
            float mo = Ms[row];
            float mn = fmaxf(mo, mx);
            float ps = __expf(sc[i][0] - mn) + __expf(sc[i][1] - mn)
                     + __expf(sc[i][2] - mn) + __expf(sc[i][3] - mn);
#pragma unroll
            for (int off = 8; off; off >>= 1)
                ps += __shfl_xor_sync(0xffffffffu, ps, off);
            if (tn == 0) {
                Ms[row] = mn;
                Ls[row] = Ls[row] * __expf(mo - mn) + ps;
            }
            // raw logits (re-read in phase 2, then overwritten with attn)
            *(float4*)&Ap[(size_t)(q0 + row) * kS + kt * 64 + tn * 4] =
                make_float4(sc[i][0], sc[i][1], sc[i][2], sc[i][3]);
        }
        __syncthreads();
    }

    if (tid < 64) Li[tid] = 1.0f / Ls[tid];
    __syncthreads();

    // ---------------- Phase 2 ----------------
    float acc[4][4] = {};
    for (int kt = 0; kt < kS / 64; kt++) {
        {
            const float4* src = (const float4*)(Vp + (size_t)kt * 64 * kDK);
#pragma unroll
            for (int r = 0; r < 4; r++) {
                int f4 = r * 256 + tid;
                int m = f4 >> 4;
                int d4 = (f4 & 15) << 2;
                *(float4*)&Pb[m][d4] = src[f4];
            }
        }
#pragma unroll
        for (int r = 0; r < 4; r++) {
            int f4 = r * 256 + tid;
            int m = f4 >> 4;
            int c4 = (f4 & 15) << 2;
            size_t gi = (size_t)(q0 + m) * kS + kt * 64 + c4;
            float4 v = *(const float4*)&Ap[gi];
            float mrow = Ms[m], li = Li[m];
            v.x = __expf(v.x - mrow) * li;
            v.y = __expf(v.y - mrow) * li;
            v.z = __expf(v.z - mrow) * li;
            v.w = __expf(v.w - mrow) * li;
            *(float4*)&Ap[gi] = v;          // final attn output
            *(float4*)&Pa[m][c4] = v;       // P tile [m][k]
        }
        __syncthreads();

#pragma unroll 16
        for (int kk = 0; kk < 64; kk++) {
            float4 vb = *(const float4*)&Pb[kk][tn * 4];
            float av[4];
#pragma unroll
            for (int i = 0; i < 4; i++) av[i] = Pa[tm * 4 + i][kk];
            float br[4] = {vb.x, vb.y, vb.z, vb.w};
#pragma unroll
            for (int i = 0; i < 4; i++)
#pragma unroll
                for (int j = 0; j < 4; j++)
                    acc[i][j] = fmaf(av[i], br[j], acc[i][j]);
        }
        __syncthreads();
    }

    // ctx -> [B,S,H*DK] row-major for the output projection
    const int b = bh >> 4;
#pragma unroll
    for (int i = 0; i < 4; i++) {
        int srow = q0 + tm * 4 + i;
        *(float4*)&g_ctx[(size_t)(b * kS + srow) * kD + h * kDK + tn * 4] =
            make_float4(acc[i][0], acc[i][1], acc[i][2], acc[i][3]);
    }
}

// ---------------------------------------------------------------------------
extern "C" void kernel_launch(void* const* d_in, const int* in_sizes, int n_in,
                              void* d_out, int out_size) {
    const float* hidden = (const float*)d_in[0];
    const float* wq     = (const float*)d_in[1];
    const float* wk     = (const float*)d_in[2];
    const float* wv     = (const float*)d_in[3];
    const float* wo     = (const float*)d_in[4];
    const float* rb     = (const float*)d_in[5];
    float* out  = (float*)d_out;
    float* attn = out + kOUT0;

    float *qp, *kp, *vp, *cp;
    cudaGetSymbolAddress((void**)&qp, g_q);
    cudaGetSymbolAddress((void**)&kp, g_k);
    cudaGetSymbolAddress((void**)&vp, g_v);
    cudaGetSymbolAddress((void**)&cp, g_ctx);

    bias_kernel<<<(kH * kNB + 255) / 256, 256>>>(rb);

    dim3 gg(kD / 64, (kB * kS) / 64);
    sgemm_kernel<<<gg, 256>>>(hidden, wq, qp, 1);
    sgemm_kernel<<<gg, 256>>>(hidden, wk, kp, 1);
    sgemm_kernel<<<gg, 256>>>(hidden, wv, vp, 1);

    attn_kernel<<<dim3(kS / 64, kBH), 256>>>(attn);

    sgemm_kernel<<<gg, 256>>>(cp, wo, out, 0);
}